// round 16
// baseline (speedup 1.0000x reference)
#include <cuda_runtime.h>
#include <math_constants.h>

// Sparsemax along last dim. (64,1024,512) fp32 -> 65536 rows x 512.
// Persistent warps (8192 warps, 8 rows each) with a cp.async double-buffered
// smem pipeline: while row r is computed out of smem stage s, row r+stride
// streams into stage s^1 (LDGSTS, L2-only). The epilogue re-reads the row
// from smem (volatile LDS -> no register-lifetime blowup, no extra DRAM).
// tau >= max-1 => candidates are x > max-1 (~6/row). Prefix-scan compaction
// into a 32-entry per-warp smem buffer + free s0 first Newton step;
// Newton on f(tau)=sum(relu(x-tau))-1 from tau0=max-1 (monotone, exact on
// piecewise-linear f). sm_103: integer redux.sync only; (count,sum) packed
// into ONE u32 redux: (k<<26)|round(t*2^20). f32x2 packed epilogue math.

#define N_COLS 512
#define WPB    2                   // warps per block (64-thread blocks)
#define NBLK   4096                // 4096*2 = 8192 warps -> 8 rows/warp
#define QSCALE 1048576.0f          // 2^20
#define QINV   (1.0f/1048576.0f)

__device__ __forceinline__ unsigned fkey(float x) {
    unsigned b = __float_as_uint(x);
    return b ^ (unsigned)(((int)b >> 31) | 0x80000000);
}
__device__ __forceinline__ float funkey(unsigned k) {
    unsigned m = (unsigned)((~((int)k >> 31)) | 0x80000000);
    return __uint_as_float(k ^ m);
}

// Volatile smem v4 load: opaque to ptxas -> no CSE, no long register lives.
__device__ __forceinline__ void lds128v(float& a, float& b, float& c, float& d,
                                        unsigned addr) {
    asm volatile("ld.shared.v4.f32 {%0,%1,%2,%3}, [%4];"
                 : "=f"(a), "=f"(b), "=f"(c), "=f"(d) : "r"(addr));
}

__global__ __launch_bounds__(64) void sparsemax_kernel(
    const float* __restrict__ x, float* __restrict__ out, int rows)
{
    __shared__ __align__(16) float buf[WPB][2][N_COLS];
    __shared__ float cand[WPB][32];

    const int wib  = threadIdx.x >> 5;
    const int lane = threadIdx.x & 31;

    const int wg     = blockIdx.x * WPB + wib;
    const int stride = gridDim.x * WPB;
    if (wg >= rows) return;

    const unsigned sb0 = (unsigned)__cvta_generic_to_shared(&buf[wib][0][0]);
    const unsigned sb1 = (unsigned)__cvta_generic_to_shared(&buf[wib][1][0]);
    const unsigned lane_off = (unsigned)lane * 16u;

    // ---- prologue: issue cp.async for first row into stage 0 ----
    {
        const float* src = x + (size_t)wg * N_COLS + lane * 4;
        #pragma unroll
        for (int i = 0; i < 4; i++) {
            asm volatile("cp.async.cg.shared.global [%0], [%1], 16;"
                         :: "r"(sb0 + (unsigned)i * 512u + lane_off),
                            "l"(src + i * 128));
        }
        asm volatile("cp.async.commit_group;");
    }

    int s = 0;
    for (int r = wg; r < rows; r += stride, s ^= 1) {
        const unsigned sbc = s ? sb1 : sb0;      // current stage
        const unsigned sbn = s ? sb0 : sb1;      // next stage

        // ---- issue next row's copy (overlaps everything below) ----
        const int rn = r + stride;
        if (rn < rows) {
            const float* src = x + (size_t)rn * N_COLS + lane * 4;
            #pragma unroll
            for (int i = 0; i < 4; i++) {
                asm volatile("cp.async.cg.shared.global [%0], [%1], 16;"
                             :: "r"(sbn + (unsigned)i * 512u + lane_off),
                                "l"(src + i * 128));
            }
        }
        asm volatile("cp.async.commit_group;");
        // wait until <=1 group pending -> current stage complete
        asm volatile("cp.async.wait_group 1;");

        // ---- max + candidate collection (phase-local z registers) ----
        float z[16];
        float ml = -CUDART_INF_F;
        #pragma unroll
        for (int i = 0; i < 4; i++) {
            lds128v(z[i*4+0], z[i*4+1], z[i*4+2], z[i*4+3],
                    sbc + (unsigned)i * 512u + lane_off);
            ml = fmaxf(ml, fmaxf(fmaxf(z[i*4+0], z[i*4+1]),
                                 fmaxf(z[i*4+2], z[i*4+3])));
        }
        const float m   = funkey(__reduce_max_sync(0xffffffffu, fkey(ml)));
        const float thr = m - 1.0f;              // tau >= thr always

        int nl = 0;
        #pragma unroll
        for (int i = 0; i < 16; i++) nl += (z[i] > thr);

        // exclusive warp prefix scan -> base slot; total via redux
        int scan = nl;
        #pragma unroll
        for (int o = 1; o < 32; o <<= 1) {
            int t = __shfl_up_sync(0xffffffffu, scan, o);
            if (lane >= o) scan += t;
        }
        int base = scan - nl;
        const int cnt = __reduce_add_sync(0xffffffffu, (unsigned)nl);

        float s0l = 0.0f;
        #pragma unroll
        for (int i = 0; i < 16; i++) {
            if (z[i] > thr) {
                s0l += z[i] - thr;
                cand[wib][base & 31] = z[i];
                base++;
            }
        }
        unsigned s0i = __reduce_add_sync(0xffffffffu,
                                         __float2uint_rn(s0l * QSCALE));
        float s0 = (float)s0i * QINV;            // >= 1 (max contributes 1)
        __syncwarp();                            // STS -> LDS visibility

        // ---- Newton ----
        float tau = thr + __fdividef(s0 - 1.0f, (float)cnt);

        if (cnt <= 32) {
            float c = (lane < cnt) ? cand[wib][lane] : -CUDART_INF_F;
            #pragma unroll 1
            for (int it = 0; it < 32; it++) {
                float t = c - tau;
                bool  p = t > 0.0f;
                unsigned packed = (p ? (1u << 26) : 0u)
                                + __float2uint_rn(fmaxf(t, 0.0f) * QSCALE);
                unsigned rr = __reduce_add_sync(0xffffffffu, packed);
                unsigned k = rr >> 26;
                if (k == 0) break;
                float su = (float)(rr & 0x03ffffffu) * QINV;
                float tn = tau + __fdividef(su - 1.0f, (float)k);
                if (!(tn > tau + 1e-6f)) {       // quantization floor
                    tau = fmaxf(tau, tn);
                    break;
                }
                tau = tn;
            }
        } else {
            // degenerate rows: re-read current stage from smem per iter
            #pragma unroll 1
            for (int it = 0; it < 64; it++) {
                float sl = 0.0f; int kl = 0;
                #pragma unroll
                for (int i = 0; i < 4; i++) {
                    float a, b, c2, d;
                    lds128v(a, b, c2, d, sbc + (unsigned)i * 512u + lane_off);
                    float t;
                    t = a  - tau; if (t > 0.0f) { sl += t; kl++; }
                    t = b  - tau; if (t > 0.0f) { sl += t; kl++; }
                    t = c2 - tau; if (t > 0.0f) { sl += t; kl++; }
                    t = d  - tau; if (t > 0.0f) { sl += t; kl++; }
                }
                unsigned si = __reduce_add_sync(0xffffffffu,
                                                __float2uint_rn(sl * QSCALE));
                int k = __reduce_add_sync(0xffffffffu, (unsigned)kl);
                if (k == 0) break;
                float su = (float)si * QINV;
                float tn = tau + __fdividef(su - 1.0f, (float)k);
                if (!(tn > tau)) break;
                tau = tn;
            }
        }

        // ---- epilogue: re-read row from smem, relu(x-tau), store ----
        unsigned long long ntau2;
        {
            unsigned nt = __float_as_uint(-tau);
            asm("mov.b64 %0, {%1, %1};" : "=l"(ntau2) : "r"(nt));
        }
        float4* po = reinterpret_cast<float4*>(out + (size_t)r * N_COLS);
        #pragma unroll
        for (int i = 0; i < 4; i++) {
            float a, b, c2, d;
            lds128v(a, b, c2, d, sbc + (unsigned)i * 512u + lane_off);
            float t0, t1, t2, t3;
            unsigned long long pa, pb, qa, qb;
            asm("mov.b64 %0, {%1, %2};" : "=l"(pa) : "f"(a),  "f"(b));
            asm("mov.b64 %0, {%1, %2};" : "=l"(pb) : "f"(c2), "f"(d));
            asm("add.rn.f32x2 %0, %1, %2;" : "=l"(qa) : "l"(pa), "l"(ntau2));
            asm("add.rn.f32x2 %0, %1, %2;" : "=l"(qb) : "l"(pb), "l"(ntau2));
            asm("mov.b64 {%0, %1}, %2;" : "=f"(t0), "=f"(t1) : "l"(qa));
            asm("mov.b64 {%0, %1}, %2;" : "=f"(t2), "=f"(t3) : "l"(qb));
            float4 v;
            v.x = fmaxf(t0, 0.0f);
            v.y = fmaxf(t1, 0.0f);
            v.z = fmaxf(t2, 0.0f);
            v.w = fmaxf(t3, 0.0f);
            __stcs(&po[i * 32 + lane], v);
        }
    }
}

extern "C" void kernel_launch(void* const* d_in, const int* in_sizes, int n_in,
                              void* d_out, int out_size)
{
    const float* x = (const float*)d_in[0];
    float* out = (float*)d_out;
    const int n = in_sizes[0];
    const int rows = n / N_COLS;

    int blocks = NBLK;
    int max_blocks = (rows + WPB - 1) / WPB;
    if (blocks > max_blocks) blocks = max_blocks;
    sparsemax_kernel<<<blocks, 32 * WPB>>>(x, out, rows);
}

// round 17
// speedup vs baseline: 1.0553x; 1.0553x over previous
#include <cuda_runtime.h>
#include <math_constants.h>

// Sparsemax along last dim. (64,1024,512) fp32 -> 65536 rows x 512.
// FINAL KERNEL (best measured wall: 44.77us; kernel 36-37us band).
//
// One warp per row, 16 fp32/lane (4x float4, __ldcs). tau >= max-1 =>
// candidates are x > max-1 (~6/row gaussian). Ballot-compact into a 32-entry
// per-warp smem buffer (clamped index); Newton on f(tau)=sum(relu(x-tau))-1
// from tau0 = max-1 (monotone from below, exact on piecewise-linear f);
// the FIRST loop iteration doubles as the s0/cnt bootstrap step.
// sm_103: integer redux.sync only -> warp max via monotone uint key;
// Newton (count,sum) in ONE u32 redux: (k<<26)|round(t*2^20)
// (fast path: t in (0,1], sum <= 32 < 64 -> no carry into k field).
// Epilogue subtraction uses packed add.rn.f32x2. 64-thread blocks (best
// measured geometry: finest wave granularity at full occupancy).

#define N_COLS 512
#define WARPS_PER_BLOCK 2          // 64-thread blocks
#define QSCALE 1048576.0f          // 2^20
#define QINV   (1.0f/1048576.0f)

__device__ __forceinline__ unsigned fkey(float x) {
    unsigned b = __float_as_uint(x);
    return b ^ (unsigned)(((int)b >> 31) | 0x80000000);
}
__device__ __forceinline__ float funkey(unsigned k) {
    unsigned m = (unsigned)((~((int)k >> 31)) | 0x80000000);
    return __uint_as_float(k ^ m);
}

__global__ __launch_bounds__(64) void sparsemax_kernel(
    const float* __restrict__ x, float* __restrict__ out, int rows)
{
    __shared__ float cand[WARPS_PER_BLOCK][32];

    const int wib  = threadIdx.x >> 5;
    const int row  = blockIdx.x * WARPS_PER_BLOCK + wib;
    if (row >= rows) return;
    const int lane = threadIdx.x & 31;
    const unsigned lt_mask = (1u << lane) - 1u;

    const float4* __restrict__ in = reinterpret_cast<const float4*>(x   + (size_t)row * N_COLS);
    float4*       __restrict__ op = reinterpret_cast<float4*>(      out + (size_t)row * N_COLS);

    float z[16];
    float ml = -CUDART_INF_F;
    #pragma unroll
    for (int i = 0; i < 4; i++) {
        float4 v = __ldcs(&in[i * 32 + lane]);   // streaming: evict-first
        z[i*4+0] = v.x; z[i*4+1] = v.y; z[i*4+2] = v.z; z[i*4+3] = v.w;
        ml = fmaxf(ml, fmaxf(fmaxf(v.x, v.y), fmaxf(v.z, v.w)));
    }
    const float m   = funkey(__reduce_max_sync(0xffffffffu, fkey(ml)));
    const float thr = m - 1.0f;                  // tau >= thr always

    // Ballot-compact candidates (z > thr) into smem (index clamped to 31;
    // fast path only used when cnt <= 32 so the clamp is harmless).
    int cnt = 0;
    #pragma unroll
    for (int i = 0; i < 16; i++) {
        bool p = z[i] > thr;
        unsigned b = __ballot_sync(0xffffffffu, p);
        if (p) {
            int pos = (cnt + __popc(b & lt_mask)) & 31;
            cand[wib][pos] = z[i];
        }
        cnt += __popc(b);
    }
    __syncwarp();                                // STS -> LDS visibility

    // Newton from tau0 = thr; the first iteration IS the s0/cnt step
    // (k = cnt, s = sum(c - thr) >= 1 since the max contributes exactly 1).
    float tau = thr;

    if (cnt <= 32) {
        float c = (lane < cnt) ? cand[wib][lane] : -CUDART_INF_F;
        #pragma unroll 1
        for (int it = 0; it < 32; it++) {
            float t = c - tau;
            bool  p = t > 0.0f;
            unsigned packed = (p ? (1u << 26) : 0u)
                            + __float2uint_rn(fmaxf(t, 0.0f) * QSCALE);
            unsigned r = __reduce_add_sync(0xffffffffu, packed);
            unsigned k = r >> 26;
            if (k == 0) break;
            float s  = (float)(r & 0x03ffffffu) * QINV;
            float tn = tau + __fdividef(s - 1.0f, (float)k);
            if (!(tn > tau + 1e-6f)) {           // quantization floor reached
                tau = fmaxf(tau, tn);
                break;
            }
            tau = tn;
        }
    } else {
        // degenerate rows (many near-max values): rescan registers
        #pragma unroll 1
        for (int it = 0; it < 64; it++) {
            float sl = 0.0f; int kl = 0;
            #pragma unroll
            for (int i = 0; i < 16; i++) {
                float t = z[i] - tau;
                if (t > 0.0f) { sl += t; kl++; }
            }
            unsigned si = __reduce_add_sync(0xffffffffu,
                                            __float2uint_rn(sl * QSCALE));
            int k = __reduce_add_sync(0xffffffffu, (unsigned)kl);
            if (k == 0) break;
            float s  = (float)si * QINV;
            float tn = tau + __fdividef(s - 1.0f, (float)k);
            if (!(tn > tau)) break;
            tau = tn;
        }
    }

    // Epilogue: packed f32x2 subtraction (8 ops for 16 elems), scalar relu.
    unsigned long long ntau2;
    {
        unsigned nt = __float_as_uint(-tau);
        asm("mov.b64 %0, {%1, %1};" : "=l"(ntau2) : "r"(nt));
    }
    #pragma unroll
    for (int i = 0; i < 4; i++) {
        float t0, t1, t2, t3;
        unsigned long long pa, pb, qa, qb;
        asm("mov.b64 %0, {%1, %2};" : "=l"(pa)
            : "f"(z[i*4+0]), "f"(z[i*4+1]));
        asm("mov.b64 %0, {%1, %2};" : "=l"(pb)
            : "f"(z[i*4+2]), "f"(z[i*4+3]));
        asm("add.rn.f32x2 %0, %1, %2;" : "=l"(qa) : "l"(pa), "l"(ntau2));
        asm("add.rn.f32x2 %0, %1, %2;" : "=l"(qb) : "l"(pb), "l"(ntau2));
        asm("mov.b64 {%0, %1}, %2;" : "=f"(t0), "=f"(t1) : "l"(qa));
        asm("mov.b64 {%0, %1}, %2;" : "=f"(t2), "=f"(t3) : "l"(qb));
        float4 v;
        v.x = fmaxf(t0, 0.0f);
        v.y = fmaxf(t1, 0.0f);
        v.z = fmaxf(t2, 0.0f);
        v.w = fmaxf(t3, 0.0f);
        __stcs(&op[i * 32 + lane], v);
    }
}

extern "C" void kernel_launch(void* const* d_in, const int* in_sizes, int n_in,
                              void* d_out, int out_size)
{
    const float* x = (const float*)d_in[0];
    float* out = (float*)d_out;
    const int n = in_sizes[0];
    const int rows = n / N_COLS;

    const int threads = 32 * WARPS_PER_BLOCK;
    const int blocks = (rows + WARPS_PER_BLOCK - 1) / WARPS_PER_BLOCK;
    sparsemax_kernel<<<blocks, threads>>>(x, out, rows);
}